// round 5
// baseline (speedup 1.0000x reference)
#include <cuda_runtime.h>
#include <cuda_fp16.h>
#include <cstdint>

#define DEVFN __device__ __forceinline__

#define NNODES 8192
#define HDIM   128
#define KNBR   48
#define CIN    384
#define KTOT   512
#define FFD    512

// -------- persistent scratch (no allocation allowed) --------
__device__ __half g_w1T[HDIM * KTOT];    // [h][k]: k<384 -> h_e part, k>=384 -> h_v part
__device__ __half g_w2T[HDIM * HDIM];    // [h_out][h_in]
__device__ __half g_w3T[HDIM * HDIM];
__device__ __half g_fwInT[FFD * HDIM];   // [f][h]
__device__ __half g_fwOutT[HDIM * FFD];  // [h][f]
__device__ float  g_h1[NNODES * HDIM];   // post-LN1 hidden

// -------- helpers --------
DEVFN uint32_t smaddr(const void* p) { return (uint32_t)__cvta_generic_to_shared(p); }

DEVFN void ldmx4(uint32_t addr, uint32_t& r0, uint32_t& r1, uint32_t& r2, uint32_t& r3) {
    asm volatile("ldmatrix.sync.aligned.m8n8.x4.shared.b16 {%0,%1,%2,%3}, [%4];\n"
                 : "=r"(r0), "=r"(r1), "=r"(r2), "=r"(r3) : "r"(addr));
}

DEVFN void mma16816(float (&c)[4], const uint32_t (&a)[4], uint32_t b0, uint32_t b1) {
    asm volatile(
        "mma.sync.aligned.m16n8k16.row.col.f32.f16.f16.f32 "
        "{%0,%1,%2,%3}, {%4,%5,%6,%7}, {%8,%9}, {%0,%1,%2,%3};\n"
        : "+f"(c[0]), "+f"(c[1]), "+f"(c[2]), "+f"(c[3])
        : "r"(a[0]), "r"(a[1]), "r"(a[2]), "r"(a[3]), "r"(b0), "r"(b1));
}

DEVFN float gelu_f(float x) { return 0.5f * x * (1.0f + erff(x * 0.70710678118654752f)); }

// A: [rows][AST] halves row-major; B: [n][BST] halves (k contiguous).
// Warp computes (MTILES*16) x (PT*16) outputs starting at (rowBase, colBase).
template <int KSTEPS, int MTILES, int PT, int AST, int BST>
DEVFN void gemm_tile(const __half* sAp, const __half* sBp, int rowBase, int colBase,
                     int lane, float (&acc)[MTILES][2 * PT][4]) {
    const int lr = lane & 15;
    const int lc = (lane >> 4) * 8;
#pragma unroll
    for (int ks = 0; ks < KSTEPS; ++ks) {
        const int kk = ks * 16 + lc;
        uint32_t a[MTILES][4];
        uint32_t b[PT][4];
#pragma unroll
        for (int mt = 0; mt < MTILES; ++mt)
            ldmx4(smaddr(sAp + (size_t)(rowBase + mt * 16 + lr) * AST + kk),
                  a[mt][0], a[mt][1], a[mt][2], a[mt][3]);
#pragma unroll
        for (int p = 0; p < PT; ++p)
            ldmx4(smaddr(sBp + (size_t)(colBase + p * 16 + lr) * BST + kk),
                  b[p][0], b[p][1], b[p][2], b[p][3]);
#pragma unroll
        for (int mt = 0; mt < MTILES; ++mt)
#pragma unroll
            for (int p = 0; p < PT; ++p) {
                mma16816(acc[mt][2 * p],     a[mt], b[p][0], b[p][2]);
                mma16816(acc[mt][2 * p + 1], a[mt], b[p][1], b[p][3]);
            }
    }
}

template <int MTILES, int NT, int DST>
DEVFN void epi_gelu_store(float (&acc)[MTILES][NT][4], const float* __restrict__ bias,
                          __half* dst, int rowBase, int colBase, int lane) {
    const int g = lane >> 2, tg = lane & 3;
#pragma unroll
    for (int mt = 0; mt < MTILES; ++mt) {
        const int r0 = rowBase + mt * 16 + g;
#pragma unroll
        for (int nt = 0; nt < NT; ++nt) {
            const int cc = colBase + nt * 8 + tg * 2;
            const float2 b = __ldg((const float2*)(bias + cc));
            float v0 = gelu_f(acc[mt][nt][0] + b.x);
            float v1 = gelu_f(acc[mt][nt][1] + b.y);
            float v2 = gelu_f(acc[mt][nt][2] + b.x);
            float v3 = gelu_f(acc[mt][nt][3] + b.y);
            *(__half2*)(dst + (size_t)r0 * DST + cc)       = __floats2half2_rn(v0, v1);
            *(__half2*)(dst + (size_t)(r0 + 8) * DST + cc) = __floats2half2_rn(v2, v3);
        }
    }
}

// -------- kernel 0: weight transpose/convert to fp16 --------
__global__ void prep_weights(const float* __restrict__ w1, const float* __restrict__ w2,
                             const float* __restrict__ w3, const float* __restrict__ fwin,
                             const float* __restrict__ fwout) {
    int i = blockIdx.x * 256 + threadIdx.x;
    if (i < 65536) {                       // w1T [h][k]  (A cols: 0..383 = h_e, 384..511 = h_v)
        int h = i >> 9, k = i & 511;
        float v = (k < 384) ? w1[(128 + k) * 128 + h] : w1[(k - 384) * 128 + h];
        g_w1T[i] = __float2half(v);
    } else if (i < 81920) {                // w2T [h][k]
        int j = i - 65536; int h = j >> 7, k = j & 127;
        g_w2T[j] = __float2half(w2[k * 128 + h]);
    } else if (i < 98304) {                // w3T
        int j = i - 81920; int h = j >> 7, k = j & 127;
        g_w3T[j] = __float2half(w3[k * 128 + h]);
    } else if (i < 163840) {               // fwInT [f][h]
        int j = i - 98304; int f = j >> 7, k = j & 127;
        g_fwInT[j] = __float2half(fwin[k * 512 + f]);
    } else if (i < 229376) {               // fwOutT [h][f]
        int j = i - 163840; int h = j >> 9, k = j & 511;
        g_fwOutT[j] = __float2half(fwout[k * 128 + h]);
    }
}

// -------- kernel 1: message MLP + mask + K-sum + residual + LN1 --------
// CTA = 4 nodes = 192 h_e rows. 256 threads = 8 warps = 4 node-warps x 2 col-warps.
#define K1_SMEM 119552
__global__ void __launch_bounds__(256) k1_msg(
    const float* __restrict__ h_v, const float* __restrict__ h_e,
    const float* __restrict__ mask_attend,
    const float* __restrict__ w1_b, const float* __restrict__ w2_b,
    const float* __restrict__ w3_b,
    const float* __restrict__ ln1_g, const float* __restrict__ ln1_b) {
    extern __shared__ char smem[];
    __half* sA    = (__half*)smem;                    // 192 x 72  (27648 B)
    __half* sB    = (__half*)(smem + 27648);          // 128 x 136 (34816 B)
    __half* sM    = (__half*)(smem + 62464);          // 192 x 136 (52224 B)
    float*  sHv   = (float*)(smem + 114688);          // 512 f
    float*  sMask = (float*)(smem + 116736);          // 192 f
    float*  sDh   = (float*)(smem + 117504);          // 512 f

    const int tid = threadIdx.x, lane = tid & 31, wid = tid >> 5;
    const int wm = wid & 3, wn = wid >> 2;
    const int rowBase = wm * 48, colBase = wn * 64;
    const size_t tileRow = (size_t)blockIdx.x * 192;
    const int nodeBase = blockIdx.x * 4;

    for (int i = tid; i < 512; i += 256) sHv[i]   = h_v[(size_t)nodeBase * 128 + i];
    for (int i = tid; i < 192; i += 256) sMask[i] = mask_attend[tileRow + i];
    __syncthreads();

    float acc[3][8][4];
#pragma unroll
    for (int a = 0; a < 3; a++)
#pragma unroll
        for (int b = 0; b < 8; b++)
#pragma unroll
            for (int c = 0; c < 4; c++) acc[a][b][c] = 0.f;

    // ---- GEMM1: [192 x 512] x [512 -> 128], K streamed in 8 chunks of 64 ----
    const float4* heBase = (const float4*)(h_e + tileRow * CIN);
    for (int kc = 0; kc < 8; ++kc) {
        if (kc < 6) {
#pragma unroll
            for (int i = 0; i < 12; ++i) {
                int idx = tid + i * 256;
                int r = idx >> 4, c4 = idx & 15;
                float4 v = __ldcs(heBase + (size_t)r * 96 + kc * 16 + c4);
                __half2* p = (__half2*)(sA + r * 72 + c4 * 4);
                p[0] = __floats2half2_rn(v.x, v.y);
                p[1] = __floats2half2_rn(v.z, v.w);
            }
        } else {
            int off = (kc - 6) * 64;
#pragma unroll
            for (int i = 0; i < 12; ++i) {
                int idx = tid + i * 256;
                int r = idx >> 4, c4 = idx & 15;
                float4 v = *(const float4*)(sHv + (r / 48) * 128 + off + c4 * 4);
                __half2* p = (__half2*)(sA + r * 72 + c4 * 4);
                p[0] = __floats2half2_rn(v.x, v.y);
                p[1] = __floats2half2_rn(v.z, v.w);
            }
        }
#pragma unroll
        for (int i = 0; i < 4; ++i) {
            int idx = tid + i * 256;
            int n = idx >> 3, j = idx & 7;
            *(uint4*)(sB + n * 136 + j * 8) = *(const uint4*)(g_w1T + n * 512 + kc * 64 + j * 8);
        }
        __syncthreads();
        gemm_tile<4, 3, 4, 72, 136>(sA, sB, rowBase, colBase, lane, acc);
        __syncthreads();
    }

    // epilogue 1: +b1, gelu -> sM ; stage w2T -> sB
    epi_gelu_store<3, 8, 136>(acc, w1_b, sM, rowBase, colBase, lane);
#pragma unroll
    for (int i = 0; i < 8; ++i) {
        int idx = tid + i * 256;
        int n = idx >> 4, j = idx & 15;
        *(uint4*)(sB + n * 136 + j * 8) = *(const uint4*)(g_w2T + n * 128 + j * 8);
    }
    __syncthreads();

    // ---- GEMM2: [192 x 128] x [128 -> 128] ----
#pragma unroll
    for (int a = 0; a < 3; a++)
#pragma unroll
        for (int b = 0; b < 8; b++)
#pragma unroll
            for (int c = 0; c < 4; c++) acc[a][b][c] = 0.f;
    gemm_tile<8, 3, 4, 136, 136>(sM, sB, rowBase, colBase, lane, acc);
    __syncthreads();

    epi_gelu_store<3, 8, 136>(acc, w2_b, sM, rowBase, colBase, lane);
#pragma unroll
    for (int i = 0; i < 8; ++i) {
        int idx = tid + i * 256;
        int n = idx >> 4, j = idx & 15;
        *(uint4*)(sB + n * 136 + j * 8) = *(const uint4*)(g_w3T + n * 128 + j * 8);
    }
    __syncthreads();

    // ---- GEMM3 ----
#pragma unroll
    for (int a = 0; a < 3; a++)
#pragma unroll
        for (int b = 0; b < 8; b++)
#pragma unroll
            for (int c = 0; c < 4; c++) acc[a][b][c] = 0.f;
    gemm_tile<8, 3, 4, 136, 136>(sM, sB, rowBase, colBase, lane, acc);

    // epilogue 3: +b3, * mask_attend, warp-local sum over the node's 48 rows
    {
        const int g = lane >> 2, tg = lane & 3;
        float mk0[3], mk1[3];
#pragma unroll
        for (int mt = 0; mt < 3; ++mt) {
            mk0[mt] = sMask[rowBase + mt * 16 + g];
            mk1[mt] = sMask[rowBase + mt * 16 + 8 + g];
        }
#pragma unroll
        for (int nt = 0; nt < 8; ++nt) {
            const int cc = colBase + nt * 8 + tg * 2;
            const float2 b3 = __ldg((const float2*)(w3_b + cc));
            float s0 = 0.f, s1 = 0.f;
#pragma unroll
            for (int mt = 0; mt < 3; ++mt) {
                s0 += (acc[mt][nt][0] + b3.x) * mk0[mt] + (acc[mt][nt][2] + b3.x) * mk1[mt];
                s1 += (acc[mt][nt][1] + b3.y) * mk0[mt] + (acc[mt][nt][3] + b3.y) * mk1[mt];
            }
#pragma unroll
            for (int o = 4; o <= 16; o <<= 1) {
                s0 += __shfl_xor_sync(0xffffffffu, s0, o);
                s1 += __shfl_xor_sync(0xffffffffu, s1, o);
            }
            if (g == 0) *(float2*)(sDh + wm * 128 + cc) = make_float2(s0, s1);
        }
    }
    __syncthreads();

    // LN1: warps 0..3, one node each
    if (wid < 4) {
        const int node = wid;
        float x[4], sum = 0.f;
#pragma unroll
        for (int j = 0; j < 4; ++j) {
            int c = lane + 32 * j;
            x[j] = sHv[node * 128 + c] + sDh[node * 128 + c] * (1.0f / 30.0f);
            sum += x[j];
        }
#pragma unroll
        for (int o = 16; o >= 1; o >>= 1) sum += __shfl_xor_sync(0xffffffffu, sum, o);
        float mu = sum * (1.0f / 128.0f);
        float vs = 0.f;
#pragma unroll
        for (int j = 0; j < 4; ++j) { float d = x[j] - mu; vs += d * d; }
#pragma unroll
        for (int o = 16; o >= 1; o >>= 1) vs += __shfl_xor_sync(0xffffffffu, vs, o);
        float rs = rsqrtf(vs * (1.0f / 128.0f) + 1e-5f);
#pragma unroll
        for (int j = 0; j < 4; ++j) {
            int c = lane + 32 * j;
            g_h1[(size_t)(nodeBase + node) * 128 + c] =
                (x[j] - mu) * rs * __ldg(ln1_g + c) + __ldg(ln1_b + c);
        }
    }
}

// -------- kernel 2: FFN + residual + LN2 + mask_v --------
// CTA = 16 nodes, 256 threads = 8 warps.
#define K2_SW 0
#define K2_SF 139264
#define K2_SH 155904
#define K2_SX 160256
#define K2_SMEM 168704
__global__ void __launch_bounds__(256) k2_ffn(
    const float* __restrict__ mask_v,
    const float* __restrict__ fw_in_b, const float* __restrict__ fw_out_b,
    const float* __restrict__ ln2_g, const float* __restrict__ ln2_b,
    float* __restrict__ out) {
    extern __shared__ char smem[];
    __half* sW = (__half*)(smem + K2_SW);   // in: [512][136], out: [128][520]
    __half* sF = (__half*)(smem + K2_SF);   // [16][520]
    __half* sH = (__half*)(smem + K2_SH);   // [16][136]
    float*  sX = (float*)(smem + K2_SX);    // [16][132]

    const int tid = threadIdx.x, lane = tid & 31, wid = tid >> 5;
    const int node0 = blockIdx.x * 16;

    for (int i = tid; i < 2048; i += 256) {
        int r = i >> 7, c = i & 127;
        sH[r * 136 + c] = __float2half(g_h1[(size_t)(node0 + r) * 128 + c]);
    }
    for (int i = tid; i < 8192; i += 256) {
        int n = i >> 4, j = i & 15;
        *(uint4*)(sW + n * 136 + j * 8) = *(const uint4*)(g_fwInT + n * 128 + j * 8);
    }
    __syncthreads();

    // GEMM-in: [16 x 128] x [128 -> 512]; warp w covers FF cols 64w..64w+63
    {
        float acc[1][8][4];
#pragma unroll
        for (int b = 0; b < 8; b++)
#pragma unroll
            for (int c = 0; c < 4; c++) acc[0][b][c] = 0.f;
        gemm_tile<8, 1, 4, 136, 136>(sH, sW, 0, wid * 64, lane, acc);
        __syncthreads();  // all sW reads done before overwrite
        epi_gelu_store<1, 8, 520>(acc, fw_in_b, sF, 0, wid * 64, lane);
    }
    for (int i = tid; i < 8192; i += 256) {
        int n = i >> 6, j = i & 63;
        *(uint4*)(sW + n * 520 + j * 8) = *(const uint4*)(g_fwOutT + n * 512 + j * 8);
    }
    __syncthreads();

    // GEMM-out: [16 x 512] x [512 -> 128]; warp w covers H cols 16w..16w+15
    {
        float acc[1][2][4];
#pragma unroll
        for (int b = 0; b < 2; b++)
#pragma unroll
            for (int c = 0; c < 4; c++) acc[0][b][c] = 0.f;
        gemm_tile<32, 1, 1, 520, 520>(sF, sW, 0, wid * 16, lane, acc);
        const int g = lane >> 2, tg = lane & 3;
#pragma unroll
        for (int nt = 0; nt < 2; ++nt) {
            const int cc = wid * 16 + nt * 8 + tg * 2;
            const float2 b = __ldg((const float2*)(fw_out_b + cc));
            const float2 r0 = *(const float2*)(g_h1 + (size_t)(node0 + g) * 128 + cc);
            const float2 r1 = *(const float2*)(g_h1 + (size_t)(node0 + 8 + g) * 128 + cc);
            sX[g * 132 + cc]           = acc[0][nt][0] + b.x + r0.x;
            sX[g * 132 + cc + 1]       = acc[0][nt][1] + b.y + r0.y;
            sX[(g + 8) * 132 + cc]     = acc[0][nt][2] + b.x + r1.x;
            sX[(g + 8) * 132 + cc + 1] = acc[0][nt][3] + b.y + r1.y;
        }
    }
    __syncthreads();

    // LN2 + mask_v + store: warp w handles rows 2w, 2w+1
#pragma unroll
    for (int rr = 0; rr < 2; ++rr) {
        const int r = wid * 2 + rr;
        float x[4], sum = 0.f;
#pragma unroll
        for (int j = 0; j < 4; ++j) { x[j] = sX[r * 132 + lane + 32 * j]; sum += x[j]; }
#pragma unroll
        for (int o = 16; o >= 1; o >>= 1) sum += __shfl_xor_sync(0xffffffffu, sum, o);
        float mu = sum * (1.0f / 128.0f);
        float vs = 0.f;
#pragma unroll
        for (int j = 0; j < 4; ++j) { float d = x[j] - mu; vs += d * d; }
#pragma unroll
        for (int o = 16; o >= 1; o >>= 1) vs += __shfl_xor_sync(0xffffffffu, vs, o);
        float rs = rsqrtf(vs * (1.0f / 128.0f) + 1e-5f);
        float mv = mask_v[node0 + r];
#pragma unroll
        for (int j = 0; j < 4; ++j) {
            int c = lane + 32 * j;
            out[(size_t)(node0 + r) * 128 + c] =
                ((x[j] - mu) * rs * __ldg(ln2_g + c) + __ldg(ln2_b + c)) * mv;
        }
    }
}

// -------- launcher --------
extern "C" void kernel_launch(void* const* d_in, const int* in_sizes, int n_in,
                              void* d_out, int out_size) {
    const float* h_v         = (const float*)d_in[0];
    const float* h_e         = (const float*)d_in[1];
    const float* mask_v      = (const float*)d_in[2];
    const float* mask_attend = (const float*)d_in[3];
    const float* w1_w        = (const float*)d_in[4];
    const float* w1_b        = (const float*)d_in[5];
    const float* w2_w        = (const float*)d_in[6];
    const float* w2_b        = (const float*)d_in[7];
    const float* w3_w        = (const float*)d_in[8];
    const float* w3_b        = (const float*)d_in[9];
    const float* ln1_g       = (const float*)d_in[10];
    const float* ln1_b       = (const float*)d_in[11];
    const float* ln2_g       = (const float*)d_in[12];
    const float* ln2_b       = (const float*)d_in[13];
    const float* fw_in_w     = (const float*)d_in[14];
    const float* fw_in_b     = (const float*)d_in[15];
    const float* fw_out_w    = (const float*)d_in[16];
    const float* fw_out_b    = (const float*)d_in[17];
    float* out = (float*)d_out;

    static bool attr_done = false;
    if (!attr_done) {
        cudaFuncSetAttribute(k1_msg, cudaFuncAttributeMaxDynamicSharedMemorySize, K1_SMEM);
        cudaFuncSetAttribute(k2_ffn, cudaFuncAttributeMaxDynamicSharedMemorySize, K2_SMEM);
        attr_done = true;
    }

    prep_weights<<<896, 256>>>(w1_w, w2_w, w3_w, fw_in_w, fw_out_w);
    k1_msg<<<NNODES / 4, 256, K1_SMEM>>>(h_v, h_e, mask_attend,
                                         w1_b, w2_b, w3_b, ln1_g, ln1_b);
    k2_ffn<<<NNODES / 16, 256, K2_SMEM>>>(mask_v, fw_in_b, fw_out_b,
                                          ln2_g, ln2_b, out);
}

// round 6
// speedup vs baseline: 1.1460x; 1.1460x over previous
#include <cuda_runtime.h>
#include <cuda_fp16.h>
#include <cstdint>

#define DEVFN __device__ __forceinline__

#define NNODES 8192
#define HDIM   128
#define KNBR   48
#define CIN    384
#define KTOT   512
#define FFD    512

// -------- persistent scratch (no allocation allowed) --------
__device__ __half g_w1T[HDIM * KTOT];    // [h][k]: k<384 -> h_e part, k>=384 -> h_v part
__device__ __half g_w2T[HDIM * HDIM];    // [h_out][h_in]
__device__ __half g_w3T[HDIM * HDIM];
__device__ __half g_fwInT[FFD * HDIM];   // [f][h]
__device__ __half g_fwOutT[HDIM * FFD];  // [h][f]
__device__ float  g_h1[NNODES * HDIM];   // post-LN1 hidden

// -------- helpers --------
DEVFN uint32_t smaddr(const void* p) { return (uint32_t)__cvta_generic_to_shared(p); }

DEVFN void ldmx4(uint32_t addr, uint32_t& r0, uint32_t& r1, uint32_t& r2, uint32_t& r3) {
    asm volatile("ldmatrix.sync.aligned.m8n8.x4.shared.b16 {%0,%1,%2,%3}, [%4];\n"
                 : "=r"(r0), "=r"(r1), "=r"(r2), "=r"(r3) : "r"(addr));
}

DEVFN void mma16816(float (&c)[4], const uint32_t (&a)[4], uint32_t b0, uint32_t b1) {
    asm volatile(
        "mma.sync.aligned.m16n8k16.row.col.f32.f16.f16.f32 "
        "{%0,%1,%2,%3}, {%4,%5,%6,%7}, {%8,%9}, {%0,%1,%2,%3};\n"
        : "+f"(c[0]), "+f"(c[1]), "+f"(c[2]), "+f"(c[3])
        : "r"(a[0]), "r"(a[1]), "r"(a[2]), "r"(a[3]), "r"(b0), "r"(b1));
}

DEVFN float gelu_f(float x) { return 0.5f * x * (1.0f + erff(x * 0.70710678118654752f)); }

// A: [rows][AST] halves row-major; B: [n][BST] halves (k contiguous).
// Warp computes (MTILES*16) x (PT*16) outputs starting at (rowBase, colBase).
// B fragment loaded per-p and consumed immediately to keep register pressure
// under 128/thread (needed for 2 CTAs/SM).
template <int KSTEPS, int MTILES, int PT, int AST, int BST>
DEVFN void gemm_tile(const __half* sAp, const __half* sBp, int rowBase, int colBase,
                     int lane, float (&acc)[MTILES][2 * PT][4]) {
    const int lr = lane & 15;
    const int lc = (lane >> 4) * 8;
#pragma unroll
    for (int ks = 0; ks < KSTEPS; ++ks) {
        const int kk = ks * 16 + lc;
        uint32_t a[MTILES][4];
#pragma unroll
        for (int mt = 0; mt < MTILES; ++mt)
            ldmx4(smaddr(sAp + (size_t)(rowBase + mt * 16 + lr) * AST + kk),
                  a[mt][0], a[mt][1], a[mt][2], a[mt][3]);
#pragma unroll
        for (int p = 0; p < PT; ++p) {
            uint32_t b0, b1, b2, b3;
            ldmx4(smaddr(sBp + (size_t)(colBase + p * 16 + lr) * BST + kk), b0, b1, b2, b3);
#pragma unroll
            for (int mt = 0; mt < MTILES; ++mt) {
                mma16816(acc[mt][2 * p],     a[mt], b0, b2);
                mma16816(acc[mt][2 * p + 1], a[mt], b1, b3);
            }
        }
    }
}

template <int MTILES, int NT, int DST>
DEVFN void epi_gelu_store(float (&acc)[MTILES][NT][4], const float* __restrict__ bias,
                          __half* dst, int rowBase, int colBase, int lane) {
    const int g = lane >> 2, tg = lane & 3;
#pragma unroll
    for (int mt = 0; mt < MTILES; ++mt) {
        const int r0 = rowBase + mt * 16 + g;
#pragma unroll
        for (int nt = 0; nt < NT; ++nt) {
            const int cc = colBase + nt * 8 + tg * 2;
            const float2 b = __ldg((const float2*)(bias + cc));
            float v0 = gelu_f(acc[mt][nt][0] + b.x);
            float v1 = gelu_f(acc[mt][nt][1] + b.y);
            float v2 = gelu_f(acc[mt][nt][2] + b.x);
            float v3 = gelu_f(acc[mt][nt][3] + b.y);
            *(__half2*)(dst + (size_t)r0 * DST + cc)       = __floats2half2_rn(v0, v1);
            *(__half2*)(dst + (size_t)(r0 + 8) * DST + cc) = __floats2half2_rn(v2, v3);
        }
    }
}

// -------- kernel 0: weight transpose/convert to fp16 --------
__global__ void prep_weights(const float* __restrict__ w1, const float* __restrict__ w2,
                             const float* __restrict__ w3, const float* __restrict__ fwin,
                             const float* __restrict__ fwout) {
    int i = blockIdx.x * 256 + threadIdx.x;
    if (i < 65536) {                       // w1T [h][k]  (A cols: 0..383 = h_e, 384..511 = h_v)
        int h = i >> 9, k = i & 511;
        float v = (k < 384) ? w1[(128 + k) * 128 + h] : w1[(k - 384) * 128 + h];
        g_w1T[i] = __float2half(v);
    } else if (i < 81920) {                // w2T [h][k]
        int j = i - 65536; int h = j >> 7, k = j & 127;
        g_w2T[j] = __float2half(w2[k * 128 + h]);
    } else if (i < 98304) {                // w3T
        int j = i - 81920; int h = j >> 7, k = j & 127;
        g_w3T[j] = __float2half(w3[k * 128 + h]);
    } else if (i < 163840) {               // fwInT [f][h]
        int j = i - 98304; int f = j >> 7, k = j & 127;
        g_fwInT[j] = __float2half(fwin[k * 512 + f]);
    } else if (i < 229376) {               // fwOutT [h][f]
        int j = i - 163840; int h = j >> 9, k = j & 511;
        g_fwOutT[j] = __float2half(fwout[k * 128 + h]);
    }
}

// -------- kernel 1: message MLP + mask + K-sum + residual + LN1 --------
// CTA = 4 nodes = 192 h_e rows. 256 threads = 8 warps = 4 node-warps x 2 col-warps.
// smem: sM [192][136] at 0 (sA [192][72] ALIASED into it — sA dead before sM
// is written), sB [128][136] at 52224, tails after. Total 91904 -> 2 CTAs/SM.
#define K1_SMEM 91904
__global__ void __launch_bounds__(256, 2) k1_msg(
    const float* __restrict__ h_v, const float* __restrict__ h_e,
    const float* __restrict__ mask_attend,
    const float* __restrict__ w1_b, const float* __restrict__ w2_b,
    const float* __restrict__ w3_b,
    const float* __restrict__ ln1_g, const float* __restrict__ ln1_b) {
    extern __shared__ char smem[];
    __half* sM    = (__half*)smem;                    // 192 x 136 (52224 B)
    __half* sA    = (__half*)smem;                    // 192 x 72  (aliased, 27648 B)
    __half* sB    = (__half*)(smem + 52224);          // 128 x 136 (34816 B)
    float*  sHv   = (float*)(smem + 87040);           // 512 f
    float*  sMask = (float*)(smem + 89088);           // 192 f
    float*  sDh   = (float*)(smem + 89856);           // 512 f

    const int tid = threadIdx.x, lane = tid & 31, wid = tid >> 5;
    const int wm = wid & 3, wn = wid >> 2;
    const int rowBase = wm * 48, colBase = wn * 64;
    const size_t tileRow = (size_t)blockIdx.x * 192;
    const int nodeBase = blockIdx.x * 4;

    for (int i = tid; i < 512; i += 256) sHv[i]   = h_v[(size_t)nodeBase * 128 + i];
    for (int i = tid; i < 192; i += 256) sMask[i] = mask_attend[tileRow + i];
    __syncthreads();

    float acc[3][8][4];
#pragma unroll
    for (int a = 0; a < 3; a++)
#pragma unroll
        for (int b = 0; b < 8; b++)
#pragma unroll
            for (int c = 0; c < 4; c++) acc[a][b][c] = 0.f;

    // ---- GEMM1: [192 x 512] x [512 -> 128], K streamed in 8 chunks of 64 ----
    const float4* heBase = (const float4*)(h_e + tileRow * CIN);
    for (int kc = 0; kc < 8; ++kc) {
        if (kc < 6) {
#pragma unroll
            for (int i = 0; i < 12; ++i) {
                int idx = tid + i * 256;
                int r = idx >> 4, c4 = idx & 15;
                float4 v = __ldcs(heBase + (size_t)r * 96 + kc * 16 + c4);
                __half2* p = (__half2*)(sA + r * 72 + c4 * 4);
                p[0] = __floats2half2_rn(v.x, v.y);
                p[1] = __floats2half2_rn(v.z, v.w);
            }
        } else {
            int off = (kc - 6) * 64;
#pragma unroll
            for (int i = 0; i < 12; ++i) {
                int idx = tid + i * 256;
                int r = idx >> 4, c4 = idx & 15;
                float4 v = *(const float4*)(sHv + (r / 48) * 128 + off + c4 * 4);
                __half2* p = (__half2*)(sA + r * 72 + c4 * 4);
                p[0] = __floats2half2_rn(v.x, v.y);
                p[1] = __floats2half2_rn(v.z, v.w);
            }
        }
#pragma unroll
        for (int i = 0; i < 4; ++i) {
            int idx = tid + i * 256;
            int n = idx >> 3, j = idx & 7;
            *(uint4*)(sB + n * 136 + j * 8) = *(const uint4*)(g_w1T + n * 512 + kc * 64 + j * 8);
        }
        __syncthreads();
        gemm_tile<4, 3, 4, 72, 136>(sA, sB, rowBase, colBase, lane, acc);
        __syncthreads();
    }

    // epilogue 1: +b1, gelu -> sM (overwrites dead sA) ; stage w2T -> sB
    epi_gelu_store<3, 8, 136>(acc, w1_b, sM, rowBase, colBase, lane);
#pragma unroll
    for (int i = 0; i < 8; ++i) {
        int idx = tid + i * 256;
        int n = idx >> 4, j = idx & 15;
        *(uint4*)(sB + n * 136 + j * 8) = *(const uint4*)(g_w2T + n * 128 + j * 8);
    }
    __syncthreads();

    // ---- GEMM2: [192 x 128] x [128 -> 128] ----
#pragma unroll
    for (int a = 0; a < 3; a++)
#pragma unroll
        for (int b = 0; b < 8; b++)
#pragma unroll
            for (int c = 0; c < 4; c++) acc[a][b][c] = 0.f;
    gemm_tile<8, 3, 4, 136, 136>(sM, sB, rowBase, colBase, lane, acc);
    __syncthreads();

    epi_gelu_store<3, 8, 136>(acc, w2_b, sM, rowBase, colBase, lane);
#pragma unroll
    for (int i = 0; i < 8; ++i) {
        int idx = tid + i * 256;
        int n = idx >> 4, j = idx & 15;
        *(uint4*)(sB + n * 136 + j * 8) = *(const uint4*)(g_w3T + n * 128 + j * 8);
    }
    __syncthreads();

    // ---- GEMM3 ----
#pragma unroll
    for (int a = 0; a < 3; a++)
#pragma unroll
        for (int b = 0; b < 8; b++)
#pragma unroll
            for (int c = 0; c < 4; c++) acc[a][b][c] = 0.f;
    gemm_tile<8, 3, 4, 136, 136>(sM, sB, rowBase, colBase, lane, acc);

    // epilogue 3: +b3, * mask_attend, warp-local sum over the node's 48 rows
    {
        const int g = lane >> 2, tg = lane & 3;
        float mk0[3], mk1[3];
#pragma unroll
        for (int mt = 0; mt < 3; ++mt) {
            mk0[mt] = sMask[rowBase + mt * 16 + g];
            mk1[mt] = sMask[rowBase + mt * 16 + 8 + g];
        }
#pragma unroll
        for (int nt = 0; nt < 8; ++nt) {
            const int cc = colBase + nt * 8 + tg * 2;
            const float2 b3 = __ldg((const float2*)(w3_b + cc));
            float s0 = 0.f, s1 = 0.f;
#pragma unroll
            for (int mt = 0; mt < 3; ++mt) {
                s0 += (acc[mt][nt][0] + b3.x) * mk0[mt] + (acc[mt][nt][2] + b3.x) * mk1[mt];
                s1 += (acc[mt][nt][1] + b3.y) * mk0[mt] + (acc[mt][nt][3] + b3.y) * mk1[mt];
            }
#pragma unroll
            for (int o = 4; o <= 16; o <<= 1) {
                s0 += __shfl_xor_sync(0xffffffffu, s0, o);
                s1 += __shfl_xor_sync(0xffffffffu, s1, o);
            }
            if (g == 0) *(float2*)(sDh + wm * 128 + cc) = make_float2(s0, s1);
        }
    }
    __syncthreads();

    // LN1: warps 0..3, one node each
    if (wid < 4) {
        const int node = wid;
        float x[4], sum = 0.f;
#pragma unroll
        for (int j = 0; j < 4; ++j) {
            int c = lane + 32 * j;
            x[j] = sHv[node * 128 + c] + sDh[node * 128 + c] * (1.0f / 30.0f);
            sum += x[j];
        }
#pragma unroll
        for (int o = 16; o >= 1; o >>= 1) sum += __shfl_xor_sync(0xffffffffu, sum, o);
        float mu = sum * (1.0f / 128.0f);
        float vs = 0.f;
#pragma unroll
        for (int j = 0; j < 4; ++j) { float d = x[j] - mu; vs += d * d; }
#pragma unroll
        for (int o = 16; o >= 1; o >>= 1) vs += __shfl_xor_sync(0xffffffffu, vs, o);
        float rs = rsqrtf(vs * (1.0f / 128.0f) + 1e-5f);
#pragma unroll
        for (int j = 0; j < 4; ++j) {
            int c = lane + 32 * j;
            g_h1[(size_t)(nodeBase + node) * 128 + c] =
                (x[j] - mu) * rs * __ldg(ln1_g + c) + __ldg(ln1_b + c);
        }
    }
}

// -------- kernel 2: FFN + residual + LN2 + mask_v --------
// CTA = 16 nodes, 256 threads = 8 warps.
#define K2_SW 0
#define K2_SF 139264
#define K2_SH 155904
#define K2_SX 160256
#define K2_SMEM 168704
__global__ void __launch_bounds__(256) k2_ffn(
    const float* __restrict__ mask_v,
    const float* __restrict__ fw_in_b, const float* __restrict__ fw_out_b,
    const float* __restrict__ ln2_g, const float* __restrict__ ln2_b,
    float* __restrict__ out) {
    extern __shared__ char smem[];
    __half* sW = (__half*)(smem + K2_SW);   // in: [512][136], out: [128][520]
    __half* sF = (__half*)(smem + K2_SF);   // [16][520]
    __half* sH = (__half*)(smem + K2_SH);   // [16][136]
    float*  sX = (float*)(smem + K2_SX);    // [16][132]

    const int tid = threadIdx.x, lane = tid & 31, wid = tid >> 5;
    const int node0 = blockIdx.x * 16;

    for (int i = tid; i < 2048; i += 256) {
        int r = i >> 7, c = i & 127;
        sH[r * 136 + c] = __float2half(g_h1[(size_t)(node0 + r) * 128 + c]);
    }
    for (int i = tid; i < 8192; i += 256) {
        int n = i >> 4, j = i & 15;
        *(uint4*)(sW + n * 136 + j * 8) = *(const uint4*)(g_fwInT + n * 128 + j * 8);
    }
    __syncthreads();

    // GEMM-in: [16 x 128] x [128 -> 512]; warp w covers FF cols 64w..64w+63
    {
        float acc[1][8][4];
#pragma unroll
        for (int b = 0; b < 8; b++)
#pragma unroll
            for (int c = 0; c < 4; c++) acc[0][b][c] = 0.f;
        gemm_tile<8, 1, 4, 136, 136>(sH, sW, 0, wid * 64, lane, acc);
        __syncthreads();  // all sW reads done before overwrite
        epi_gelu_store<1, 8, 520>(acc, fw_in_b, sF, 0, wid * 64, lane);
    }
    for (int i = tid; i < 8192; i += 256) {
        int n = i >> 6, j = i & 63;
        *(uint4*)(sW + n * 520 + j * 8) = *(const uint4*)(g_fwOutT + n * 512 + j * 8);
    }
    __syncthreads();

    // GEMM-out: [16 x 512] x [512 -> 128]; warp w covers H cols 16w..16w+15
    {
        float acc[1][2][4];
#pragma unroll
        for (int b = 0; b < 2; b++)
#pragma unroll
            for (int c = 0; c < 4; c++) acc[0][b][c] = 0.f;
        gemm_tile<32, 1, 1, 520, 520>(sF, sW, 0, wid * 16, lane, acc);
        const int g = lane >> 2, tg = lane & 3;
#pragma unroll
        for (int nt = 0; nt < 2; ++nt) {
            const int cc = wid * 16 + nt * 8 + tg * 2;
            const float2 b = __ldg((const float2*)(fw_out_b + cc));
            const float2 r0 = *(const float2*)(g_h1 + (size_t)(node0 + g) * 128 + cc);
            const float2 r1 = *(const float2*)(g_h1 + (size_t)(node0 + 8 + g) * 128 + cc);
            sX[g * 132 + cc]           = acc[0][nt][0] + b.x + r0.x;
            sX[g * 132 + cc + 1]       = acc[0][nt][1] + b.y + r0.y;
            sX[(g + 8) * 132 + cc]     = acc[0][nt][2] + b.x + r1.x;
            sX[(g + 8) * 132 + cc + 1] = acc[0][nt][3] + b.y + r1.y;
        }
    }
    __syncthreads();

    // LN2 + mask_v + store: warp w handles rows 2w, 2w+1
#pragma unroll
    for (int rr = 0; rr < 2; ++rr) {
        const int r = wid * 2 + rr;
        float x[4], sum = 0.f;
#pragma unroll
        for (int j = 0; j < 4; ++j) { x[j] = sX[r * 132 + lane + 32 * j]; sum += x[j]; }
#pragma unroll
        for (int o = 16; o >= 1; o >>= 1) sum += __shfl_xor_sync(0xffffffffu, sum, o);
        float mu = sum * (1.0f / 128.0f);
        float vs = 0.f;
#pragma unroll
        for (int j = 0; j < 4; ++j) { float d = x[j] - mu; vs += d * d; }
#pragma unroll
        for (int o = 16; o >= 1; o >>= 1) vs += __shfl_xor_sync(0xffffffffu, vs, o);
        float rs = rsqrtf(vs * (1.0f / 128.0f) + 1e-5f);
        float mv = mask_v[node0 + r];
#pragma unroll
        for (int j = 0; j < 4; ++j) {
            int c = lane + 32 * j;
            out[(size_t)(node0 + r) * 128 + c] =
                ((x[j] - mu) * rs * __ldg(ln2_g + c) + __ldg(ln2_b + c)) * mv;
        }
    }
}

// -------- launcher --------
extern "C" void kernel_launch(void* const* d_in, const int* in_sizes, int n_in,
                              void* d_out, int out_size) {
    const float* h_v         = (const float*)d_in[0];
    const float* h_e         = (const float*)d_in[1];
    const float* mask_v      = (const float*)d_in[2];
    const float* mask_attend = (const float*)d_in[3];
    const float* w1_b        = (const float*)d_in[5];
    const float* w2_b        = (const float*)d_in[7];
    const float* w3_b        = (const float*)d_in[9];
    const float* ln1_g       = (const float*)d_in[10];
    const float* ln1_b       = (const float*)d_in[11];
    const float* ln2_g       = (const float*)d_in[12];
    const float* ln2_b       = (const float*)d_in[13];
    const float* fw_in_b     = (const float*)d_in[15];
    const float* fw_out_b    = (const float*)d_in[17];
    float* out = (float*)d_out;

    static bool attr_done = false;
    if (!attr_done) {
        cudaFuncSetAttribute(k1_msg, cudaFuncAttributeMaxDynamicSharedMemorySize, K1_SMEM);
        cudaFuncSetAttribute(k2_ffn, cudaFuncAttributeMaxDynamicSharedMemorySize, K2_SMEM);
        attr_done = true;
    }

    prep_weights<<<896, 256>>>((const float*)d_in[4], (const float*)d_in[6],
                               (const float*)d_in[8], (const float*)d_in[14],
                               (const float*)d_in[16]);
    k1_msg<<<NNODES / 4, 256, K1_SMEM>>>(h_v, h_e, mask_attend,
                                         w1_b, w2_b, w3_b, ln1_g, ln1_b);
    k2_ffn<<<NNODES / 16, 256, K2_SMEM>>>(mask_v, fw_in_b, fw_out_b,
                                          ln2_g, ln2_b, out);
}